// round 7
// baseline (speedup 1.0000x reference)
#include <cuda_runtime.h>
#include <cstdint>

#define NN    8192
#define EMB   256
#define NHID  64
#define LOG2E 1.4426950408889634f

// Scratch (static device arrays are allowed; no allocation).
__device__ float g_h[NN * NHID];   // h = input @ W       (2 MB, L2-resident)
__device__ float g_ss[NN];         // s_src * log2e
__device__ float g_sd[NN];         // s_dst * log2e

// ---------------------------------------------------------------------------
// FFMA2: packed f32x2 fma (acc.xy += w.xy * h.xy). ptxas will not auto-fuse;
// must come from PTX fma.rn.f32x2 (sm_100+).
// ---------------------------------------------------------------------------
__device__ __forceinline__ void fma2(unsigned long long& acc,
                                     unsigned long long w,
                                     unsigned long long h) {
    asm("fma.rn.f32x2 %0, %1, %2, %0;" : "+l"(acc) : "l"(w), "l"(h));
}

__device__ __forceinline__ unsigned long long dup_f32(float w) {
    unsigned long long d;
    asm("mov.b64 %0, {%1, %1};" : "=l"(d) : "r"(__float_as_uint(w)));
    return d;
}

__device__ __forceinline__ float ex2_approx(float x) {
    float r;
    asm("ex2.approx.ftz.f32 %0, %1;" : "=f"(r) : "f"(x));
    return r;
}

// ---------------------------------------------------------------------------
// Kernel A: h[8192,64] = input[8192,256] @ W[256,64]
// 256 blocks x 256 threads, 32 rows/block. W + input tile staged in smem.
// ---------------------------------------------------------------------------
__global__ __launch_bounds__(256) void kA(const float* __restrict__ input,
                                          const float* __restrict__ W) {
    extern __shared__ float smemA[];
    float* W_s  = smemA;                 // 256*64 = 16384 floats (64 KB)
    float* in_s = smemA + EMB * NHID;    // 32*256 =  8192 floats (32 KB)

    const int t = threadIdx.x;
    const int rowbase = blockIdx.x * 32;

    float4*       Ws4 = (float4*)W_s;
    const float4* Wg4 = (const float4*)W;
#pragma unroll
    for (int u = 0; u < 16; u++) Ws4[t + u * 256] = Wg4[t + u * 256];

    float4*       is4 = (float4*)in_s;
    const float4* ig4 = (const float4*)(input + (size_t)rowbase * EMB);
#pragma unroll
    for (int u = 0; u < 8; u++) is4[t + u * 256] = ig4[t + u * 256];
    __syncthreads();

    const int dg = t & 15;            // dim group: dims 4*dg .. 4*dg+3
    const int r0 = (t >> 4) * 2;      // rows r0, r0+1
    float4 acc0 = make_float4(0.f, 0.f, 0.f, 0.f);
    float4 acc1 = make_float4(0.f, 0.f, 0.f, 0.f);

#pragma unroll 4
    for (int k = 0; k < EMB; k++) {
        float4 wv = Ws4[k * 16 + dg];
        float  a0 = in_s[r0 * EMB + k];
        float  a1 = in_s[(r0 + 1) * EMB + k];
        acc0.x += a0 * wv.x; acc0.y += a0 * wv.y; acc0.z += a0 * wv.z; acc0.w += a0 * wv.w;
        acc1.x += a1 * wv.x; acc1.y += a1 * wv.y; acc1.z += a1 * wv.z; acc1.w += a1 * wv.w;
    }

    *(float4*)&g_h[(size_t)(rowbase + r0) * NHID + dg * 4]     = acc0;
    *(float4*)&g_h[(size_t)(rowbase + r0 + 1) * NHID + dg * 4] = acc1;
}

// ---------------------------------------------------------------------------
// Kernel B: s_src[i] = (h[i,:] . a[0:64]) * log2e ; s_dst similarly with a[64:128]
// One warp per row. 1024 blocks x 256 threads.
// ---------------------------------------------------------------------------
__global__ __launch_bounds__(256) void kB(const float* __restrict__ a) {
    const int lane = threadIdx.x & 31;
    const int warp = threadIdx.x >> 5;
    const int i    = blockIdx.x * 8 + warp;

    float h0 = g_h[(size_t)i * NHID + lane];
    float h1 = g_h[(size_t)i * NHID + 32 + lane];
    float a0 = __ldg(a + lane),      a1 = __ldg(a + 32 + lane);
    float b0 = __ldg(a + 64 + lane), b1 = __ldg(a + 96 + lane);

    float s1 = h0 * a0 + h1 * a1;
    float s2 = h0 * b0 + h1 * b1;
#pragma unroll
    for (int o = 16; o > 0; o >>= 1) {
        s1 += __shfl_xor_sync(0xffffffffu, s1, o);
        s2 += __shfl_xor_sync(0xffffffffu, s2, o);
    }
    if (lane == 0) {
        g_ss[i] = s1 * LOG2E;
        g_sd[i] = s2 * LOG2E;
    }
}

// ---------------------------------------------------------------------------
// Kernel C: fused masked-softmax attention: out = softmax(mask(e)) @ h
// 128 CTAs x 256 threads. 64 rows/CTA, K-tile = 128.
// smem: h tile [128][64] f32 (32KB) + w tile [64][128] as dup'd f32x2 (64KB).
// GEMM: warp owns 8 rows x 64 dims; lane owns 2 dims (one f32x2 accumulator/row).
// ---------------------------------------------------------------------------
__global__ __launch_bounds__(256, 1) void kC(const int* __restrict__ adj,
                                             float* __restrict__ out) {
    extern __shared__ char smem[];
    float*              h_s  = (float*)smem;                                  // 32 KB
    unsigned long long* w_s  = (unsigned long long*)(smem + 32768);           // 64 KB
    float*              sS_s = (float*)(smem + 32768 + 65536);                // 64 f
    float*              l_s  = sS_s + 64;                                     // 64 f

    const int t    = threadIdx.x;
    const int lane = t & 31;
    const int warp = t >> 5;
    const int rowbase = blockIdx.x * 64;

    if (t < 64) sS_s[t] = g_ss[rowbase + t];

    unsigned long long acc[8];
#pragma unroll
    for (int r = 0; r < 8; r++) acc[r] = 0ULL;
    float lrow[8];
#pragma unroll
    for (int r = 0; r < 8; r++) lrow[r] = 0.f;

    const unsigned long long* hs64 = (const unsigned long long*)h_s;
    __syncthreads();

    for (int jb = 0; jb < NN; jb += 128) {
        // ---- load h tile (128 x 64 floats = 2048 float4) ----
        {
            const float4* hsrc = (const float4*)(g_h + (size_t)jb * NHID);
            float4*       hdst = (float4*)h_s;
#pragma unroll
            for (int u = 0; u < 8; u++) hdst[t + u * 256] = hsrc[t + u * 256];
        }

        // ---- phase 1: compute w tile + row-sum partials ----
        const int j0 = lane * 4;
        const float4 sdv = *(const float4*)(g_sd + jb + j0);
#pragma unroll
        for (int it = 0; it < 8; it++) {
            const int i = warp + it * 8;
            int4 av = *(const int4*)(adj + (size_t)(rowbase + i) * NN + jb + j0);
            const float si = sS_s[i];
            float x0 = si + sdv.x, x1 = si + sdv.y, x2 = si + sdv.z, x3 = si + sdv.w;
            // exp(leakyrelu(x)) with log2e prefolded: ex2(max(X, 0.2X))
            float w0 = ex2_approx(fmaxf(x0, 0.2f * x0));
            float w1 = ex2_approx(fmaxf(x1, 0.2f * x1));
            float w2 = ex2_approx(fmaxf(x2, 0.2f * x2));
            float w3 = ex2_approx(fmaxf(x3, 0.2f * x3));
            w0 = (av.x > 0) ? w0 : 0.f;
            w1 = (av.y > 0) ? w1 : 0.f;
            w2 = (av.z > 0) ? w2 : 0.f;
            w3 = (av.w > 0) ? w3 : 0.f;

            ulonglong2* dst = (ulonglong2*)&w_s[i * 128 + j0];
            dst[0] = make_ulonglong2(dup_f32(w0), dup_f32(w1));
            dst[1] = make_ulonglong2(dup_f32(w2), dup_f32(w3));

            float ws = (w0 + w1) + (w2 + w3);
#pragma unroll
            for (int o = 16; o > 0; o >>= 1)
                ws += __shfl_xor_sync(0xffffffffu, ws, o);
            lrow[it] += ws;   // valid on every lane; lane 0 writes later
        }
        __syncthreads();

        // ---- phase 2: f32x2 GEMM over this tile ----
        const unsigned long long* wr = &w_s[(warp * 8) * 128];
#pragma unroll 2
        for (int j = 0; j < 128; j += 4) {
            unsigned long long hj0 = hs64[(j + 0) * 32 + lane];
            unsigned long long hj1 = hs64[(j + 1) * 32 + lane];
            unsigned long long hj2 = hs64[(j + 2) * 32 + lane];
            unsigned long long hj3 = hs64[(j + 3) * 32 + lane];
#pragma unroll
            for (int r = 0; r < 8; r++) {
                ulonglong2 wa = *(const ulonglong2*)&wr[r * 128 + j];
                ulonglong2 wb = *(const ulonglong2*)&wr[r * 128 + j + 2];
                fma2(acc[r], wa.x, hj0);
                fma2(acc[r], wa.y, hj1);
                fma2(acc[r], wb.x, hj2);
                fma2(acc[r], wb.y, hj3);
            }
        }
        __syncthreads();
    }

    // ---- epilogue: normalize and store ----
    if (lane == 0) {
#pragma unroll
        for (int it = 0; it < 8; it++) l_s[warp + it * 8] = lrow[it];
    }
    __syncthreads();

#pragma unroll
    for (int r = 0; r < 8; r++) {
        const int i  = warp * 8 + r;
        const float inv = 1.0f / l_s[i];
        unsigned long long v = acc[r];
        float lo = __uint_as_float((unsigned)(v & 0xffffffffULL)) * inv;
        float hi = __uint_as_float((unsigned)(v >> 32)) * inv;
        *(float2*)&out[(size_t)(rowbase + i) * NHID + lane * 2] = make_float2(lo, hi);
    }
}

// ---------------------------------------------------------------------------
extern "C" void kernel_launch(void* const* d_in, const int* in_sizes, int n_in,
                              void* d_out, int out_size) {
    const float* input = (const float*)d_in[0];   // [8192, 256] f32
    const int*   adj   = (const int*)d_in[1];     // [8192, 8192] i32
    const float* W     = (const float*)d_in[2];   // [256, 64] f32
    const float* a     = (const float*)d_in[3];   // [128] f32
    float* out = (float*)d_out;                   // [8192, 64] f32

    const int smemA = (EMB * NHID + 32 * EMB) * sizeof(float);      // 96 KB
    const int smemC = 32768 + 65536 + 2 * 64 * (int)sizeof(float);  // ~98.8 KB
    cudaFuncSetAttribute(kA, cudaFuncAttributeMaxDynamicSharedMemorySize, smemA);
    cudaFuncSetAttribute(kC, cudaFuncAttributeMaxDynamicSharedMemorySize, smemC);

    kA<<<NN / 32, 256, smemA>>>(input, W);
    kB<<<NN / 8, 256>>>(a);
    kC<<<NN / 64, 256, smemC>>>(adj, out);
}

// round 9
// speedup vs baseline: 1.1942x; 1.1942x over previous
#include <cuda_runtime.h>
#include <cstdint>

#define NN    8192
#define EMB   256
#define NHID  64
#define LOG2E 1.4426950408889634f
#define RPC   56          // rows per CTA in kC
#define JT    128         // j-tile

// Scratch (static device arrays; no allocation).
__device__ float g_h[NN * NHID];   // h = input @ W  (2 MB, L2-resident)
__device__ float g_ss[NN];         // s_src * log2e
__device__ float g_sd[NN];         // s_dst * log2e

__device__ __forceinline__ void fma2(unsigned long long& acc,
                                     unsigned long long w,
                                     unsigned long long h) {
    asm("fma.rn.f32x2 %0, %1, %2, %0;" : "+l"(acc) : "l"(w), "l"(h));
}
__device__ __forceinline__ unsigned long long dup_f32(float w) {
    unsigned long long d;
    asm("mov.b64 %0, {%1, %1};" : "=l"(d) : "r"(__float_as_uint(w)));
    return d;
}
__device__ __forceinline__ float ex2_approx(float x) {
    float r;
    asm("ex2.approx.ftz.f32 %0, %1;" : "=f"(r) : "f"(x));
    return r;
}

// ---------------------------------------------------------------------------
// Kernel A: h = input @ W, fused with s_src/s_dst computation (kB folded in).
// 256 blocks x 256 threads, 32 rows/block.
// ---------------------------------------------------------------------------
__global__ __launch_bounds__(256) void kA(const float* __restrict__ input,
                                          const float* __restrict__ W,
                                          const float* __restrict__ a) {
    extern __shared__ float smemA[];
    float* W_s  = smemA;                 // 256*64 floats (64 KB)
    float* in_s = smemA + EMB * NHID;    // 32*256 floats (32 KB)

    const int t = threadIdx.x;
    const int rowbase = blockIdx.x * 32;

    float4*       Ws4 = (float4*)W_s;
    const float4* Wg4 = (const float4*)W;
#pragma unroll
    for (int u = 0; u < 16; u++) Ws4[t + u * 256] = Wg4[t + u * 256];

    float4*       is4 = (float4*)in_s;
    const float4* ig4 = (const float4*)(input + (size_t)rowbase * EMB);
#pragma unroll
    for (int u = 0; u < 8; u++) is4[t + u * 256] = ig4[t + u * 256];
    __syncthreads();

    const int dg = t & 15;            // dims 4*dg .. 4*dg+3
    const int r0 = (t >> 4) * 2;      // rows r0, r0+1
    float4 acc0 = make_float4(0.f, 0.f, 0.f, 0.f);
    float4 acc1 = make_float4(0.f, 0.f, 0.f, 0.f);

#pragma unroll 4
    for (int k = 0; k < EMB; k++) {
        float4 wv = Ws4[k * 16 + dg];
        float  a0 = in_s[r0 * EMB + k];
        float  a1 = in_s[(r0 + 1) * EMB + k];
        acc0.x += a0 * wv.x; acc0.y += a0 * wv.y; acc0.z += a0 * wv.z; acc0.w += a0 * wv.w;
        acc1.x += a1 * wv.x; acc1.y += a1 * wv.y; acc1.z += a1 * wv.z; acc1.w += a1 * wv.w;
    }

    *(float4*)&g_h[(size_t)(rowbase + r0) * NHID + dg * 4]     = acc0;
    *(float4*)&g_h[(size_t)(rowbase + r0 + 1) * NHID + dg * 4] = acc1;

    // ---- fused s_src / s_dst ----
    const float as0 = __ldg(a + 4 * dg),      as1 = __ldg(a + 4 * dg + 1);
    const float as2 = __ldg(a + 4 * dg + 2),  as3 = __ldg(a + 4 * dg + 3);
    const float ad0 = __ldg(a + 64 + 4 * dg), ad1 = __ldg(a + 64 + 4 * dg + 1);
    const float ad2 = __ldg(a + 64 + 4 * dg + 2), ad3 = __ldg(a + 64 + 4 * dg + 3);

    float p0s = acc0.x * as0 + acc0.y * as1 + acc0.z * as2 + acc0.w * as3;
    float p0d = acc0.x * ad0 + acc0.y * ad1 + acc0.z * ad2 + acc0.w * ad3;
    float p1s = acc1.x * as0 + acc1.y * as1 + acc1.z * as2 + acc1.w * as3;
    float p1d = acc1.x * ad0 + acc1.y * ad1 + acc1.z * ad2 + acc1.w * ad3;
#pragma unroll
    for (int o = 8; o > 0; o >>= 1) {
        p0s += __shfl_down_sync(0xffffffffu, p0s, o, 16);
        p0d += __shfl_down_sync(0xffffffffu, p0d, o, 16);
        p1s += __shfl_down_sync(0xffffffffu, p1s, o, 16);
        p1d += __shfl_down_sync(0xffffffffu, p1d, o, 16);
    }
    if (dg == 0) {
        g_ss[rowbase + r0]     = p0s * LOG2E;
        g_sd[rowbase + r0]     = p0d * LOG2E;
        g_ss[rowbase + r0 + 1] = p1s * LOG2E;
        g_sd[rowbase + r0 + 1] = p1d * LOG2E;
    }
}

// ---------------------------------------------------------------------------
// Kernel C: fused masked-softmax attention, software-pipelined.
// 147 CTAs x 256 threads, 56 rows/CTA, j-tile = 128.
// Phase-1 rows: i = warp + it*8 (it<7). GEMM rows: warp*7 .. warp*7+6.
// Row-sum: per-lane partials across all tiles, single reduce in epilogue.
// ---------------------------------------------------------------------------
__global__ __launch_bounds__(256, 1) void kC(const int* __restrict__ adj,
                                             float* __restrict__ out) {
    extern __shared__ char smem[];
    float*              h_s = (float*)smem;                         // 32 KB
    unsigned long long* w_s = (unsigned long long*)(smem + 32768);  // 56*128*8 = 57344 B
    float*              l_s = (float*)(smem + 32768 + 57344);       // 56 floats

    const int t    = threadIdx.x;
    const int lane = t & 31;
    const int warp = t >> 5;
    const int rowbase = blockIdx.x * RPC;
    const int j0 = lane * 4;

    // per-thread phase-1 row set (clamped for the partial last CTA)
    int   rowg[7];
    float si[7];
#pragma unroll
    for (int it = 0; it < 7; it++) {
        int rg = rowbase + warp + it * 8;
        rowg[it] = (rg < NN) ? rg : (NN - 1);
        si[it]   = g_ss[rowg[it]];
    }

    unsigned long long acc[7];
    float lrow[7];
#pragma unroll
    for (int r = 0; r < 7; r++) { acc[r] = 0ULL; lrow[r] = 0.f; }

    const unsigned long long* hs64 = (const unsigned long long*)h_s;
    float4*                   hdst = (float4*)h_s;

    // ---- prologue: prefetch tile 0 and compute its w values ----
    int4   apf[7];
    float4 hpf[8];
    float  wv[28];
    float4 sdv = *(const float4*)(g_sd + j0);
    {
        const float4* hsrc = (const float4*)g_h;
#pragma unroll
        for (int u = 0; u < 8; u++) hpf[u] = hsrc[t + u * 256];
#pragma unroll
        for (int it = 0; it < 7; it++)
            apf[it] = *(const int4*)(adj + (size_t)rowg[it] * NN + j0);
#pragma unroll
        for (int it = 0; it < 7; it++) {
            float x0 = si[it] + sdv.x, x1 = si[it] + sdv.y;
            float x2 = si[it] + sdv.z, x3 = si[it] + sdv.w;
            float w0 = ex2_approx(fmaxf(x0, 0.2f * x0));
            float w1 = ex2_approx(fmaxf(x1, 0.2f * x1));
            float w2 = ex2_approx(fmaxf(x2, 0.2f * x2));
            float w3 = ex2_approx(fmaxf(x3, 0.2f * x3));
            w0 = (apf[it].x > 0) ? w0 : 0.f;
            w1 = (apf[it].y > 0) ? w1 : 0.f;
            w2 = (apf[it].z > 0) ? w2 : 0.f;
            w3 = (apf[it].w > 0) ? w3 : 0.f;
            wv[it * 4 + 0] = w0; wv[it * 4 + 1] = w1;
            wv[it * 4 + 2] = w2; wv[it * 4 + 3] = w3;
            lrow[it] += (w0 + w1) + (w2 + w3);   // per-lane partial, reduced at end
        }
    }

    const unsigned long long* wr = &w_s[(warp * 7) * 128];

    for (int jb = 0; jb < NN; jb += JT) {
        // ---- commit prefetched tile to smem ----
#pragma unroll
        for (int u = 0; u < 8; u++) hdst[t + u * 256] = hpf[u];
#pragma unroll
        for (int it = 0; it < 7; it++) {
            int i = warp + it * 8;
            ulonglong2* d = (ulonglong2*)&w_s[i * 128 + j0];
            d[0] = make_ulonglong2(dup_f32(wv[it * 4 + 0]), dup_f32(wv[it * 4 + 1]));
            d[1] = make_ulonglong2(dup_f32(wv[it * 4 + 2]), dup_f32(wv[it * 4 + 3]));
        }
        __syncthreads();

        const int  jn   = jb + JT;
        const bool more = jn < NN;
        if (more) {
            const float4* hsrc = (const float4*)(g_h + (size_t)jn * NHID);
#pragma unroll
            for (int u = 0; u < 8; u++) hpf[u] = hsrc[t + u * 256];
#pragma unroll
            for (int it = 0; it < 7; it++)
                apf[it] = *(const int4*)(adj + (size_t)rowg[it] * NN + jn + j0);
            sdv = *(const float4*)(g_sd + jn + j0);
        }

        // ---- GEMM first half (covers LDG latency) ----
#pragma unroll 4
        for (int j = 0; j < 64; j += 4) {
            unsigned long long hj0 = hs64[(j + 0) * 32 + lane];
            unsigned long long hj1 = hs64[(j + 1) * 32 + lane];
            unsigned long long hj2 = hs64[(j + 2) * 32 + lane];
            unsigned long long hj3 = hs64[(j + 3) * 32 + lane];
#pragma unroll
            for (int r = 0; r < 7; r++) {
                ulonglong2 wa = *(const ulonglong2*)&wr[r * 128 + j];
                ulonglong2 wb = *(const ulonglong2*)&wr[r * 128 + j + 2];
                fma2(acc[r], wa.x, hj0);
                fma2(acc[r], wa.y, hj1);
                fma2(acc[r], wb.x, hj2);
                fma2(acc[r], wb.y, hj3);
            }
        }

        // ---- compute next tile's w (MUFU overlaps second GEMM half) ----
        if (more) {
#pragma unroll
            for (int it = 0; it < 7; it++) {
                float x0 = si[it] + sdv.x, x1 = si[it] + sdv.y;
                float x2 = si[it] + sdv.z, x3 = si[it] + sdv.w;
                float w0 = ex2_approx(fmaxf(x0, 0.2f * x0));
                float w1 = ex2_approx(fmaxf(x1, 0.2f * x1));
                float w2 = ex2_approx(fmaxf(x2, 0.2f * x2));
                float w3 = ex2_approx(fmaxf(x3, 0.2f * x3));
                w0 = (apf[it].x > 0) ? w0 : 0.f;
                w1 = (apf[it].y > 0) ? w1 : 0.f;
                w2 = (apf[it].z > 0) ? w2 : 0.f;
                w3 = (apf[it].w > 0) ? w3 : 0.f;
                wv[it * 4 + 0] = w0; wv[it * 4 + 1] = w1;
                wv[it * 4 + 2] = w2; wv[it * 4 + 3] = w3;
                lrow[it] += (w0 + w1) + (w2 + w3);
            }
        }

        // ---- GEMM second half ----
#pragma unroll 4
        for (int j = 64; j < 128; j += 4) {
            unsigned long long hj0 = hs64[(j + 0) * 32 + lane];
            unsigned long long hj1 = hs64[(j + 1) * 32 + lane];
            unsigned long long hj2 = hs64[(j + 2) * 32 + lane];
            unsigned long long hj3 = hs64[(j + 3) * 32 + lane];
#pragma unroll
            for (int r = 0; r < 7; r++) {
                ulonglong2 wa = *(const ulonglong2*)&wr[r * 128 + j];
                ulonglong2 wb = *(const ulonglong2*)&wr[r * 128 + j + 2];
                fma2(acc[r], wa.x, hj0);
                fma2(acc[r], wa.y, hj1);
                fma2(acc[r], wb.x, hj2);
                fma2(acc[r], wb.y, hj3);
            }
        }
        __syncthreads();
    }

    // ---- epilogue: single row-sum reduce, normalize, store ----
#pragma unroll
    for (int it = 0; it < 7; it++) {
        float s = lrow[it];
#pragma unroll
        for (int o = 16; o > 0; o >>= 1)
            s += __shfl_xor_sync(0xffffffffu, s, o);
        if (lane == 0) l_s[warp + it * 8] = s;
    }
    __syncthreads();

#pragma unroll
    for (int r = 0; r < 7; r++) {
        const int i  = warp * 7 + r;
        const int rg = rowbase + i;
        if (rg < NN) {
            const float inv = 1.0f / l_s[i];
            unsigned long long v = acc[r];
            float lo = __uint_as_float((unsigned)(v & 0xffffffffULL)) * inv;
            float hi = __uint_as_float((unsigned)(v >> 32)) * inv;
            *(float2*)&out[(size_t)rg * NHID + lane * 2] = make_float2(lo, hi);
        }
    }
}

// ---------------------------------------------------------------------------
extern "C" void kernel_launch(void* const* d_in, const int* in_sizes, int n_in,
                              void* d_out, int out_size) {
    const float* input = (const float*)d_in[0];   // [8192, 256] f32
    const int*   adj   = (const int*)d_in[1];     // [8192, 8192] i32
    const float* W     = (const float*)d_in[2];   // [256, 64] f32
    const float* a     = (const float*)d_in[3];   // [128] f32
    float* out = (float*)d_out;                   // [8192, 64] f32

    const int smemA = (EMB * NHID + 32 * EMB) * sizeof(float);     // 96 KB
    const int smemC = 32768 + 57344 + 64 * (int)sizeof(float);     // ~88 KB
    cudaFuncSetAttribute(kA, cudaFuncAttributeMaxDynamicSharedMemorySize, smemA);
    cudaFuncSetAttribute(kC, cudaFuncAttributeMaxDynamicSharedMemorySize, smemC);

    kA<<<NN / 32, 256, smemA>>>(input, W, a);
    kC<<<(NN + RPC - 1) / RPC, 256, smemC>>>(adj, out);
}

// round 10
// speedup vs baseline: 1.5322x; 1.2831x over previous
#include <cuda_runtime.h>
#include <cstdint>

#define NN    8192
#define EMB   256
#define NHID  64
#define LOG2E 1.4426950408889634f
#define RPC   56          // rows per CTA in kC
#define JT    128         // j-tile

// Scratch (static device arrays; no allocation).
__device__ float g_h[NN * NHID];   // h = input @ W  (2 MB, L2-resident)
__device__ float g_ss[NN];         // s_src * log2e
__device__ float g_sd[NN];         // s_dst * log2e

__device__ __forceinline__ void fma2(unsigned long long& acc,
                                     unsigned long long w,
                                     unsigned long long h) {
    asm("fma.rn.f32x2 %0, %1, %2, %0;" : "+l"(acc) : "l"(w), "l"(h));
}
__device__ __forceinline__ float ex2_approx(float x) {
    float r;
    asm("ex2.approx.ftz.f32 %0, %1;" : "=f"(r) : "f"(x));
    return r;
}

// ---------------------------------------------------------------------------
// Kernel A: h = input @ W, fused with s_src/s_dst computation.
// 256 blocks x 256 threads, 32 rows/block.  (17us; not the bottleneck)
// ---------------------------------------------------------------------------
__global__ __launch_bounds__(256) void kA(const float* __restrict__ input,
                                          const float* __restrict__ W,
                                          const float* __restrict__ a) {
    extern __shared__ float smemA[];
    float* W_s  = smemA;                 // 256*64 floats (64 KB)
    float* in_s = smemA + EMB * NHID;    // 32*256 floats (32 KB)

    const int t = threadIdx.x;
    const int rowbase = blockIdx.x * 32;

    float4*       Ws4 = (float4*)W_s;
    const float4* Wg4 = (const float4*)W;
#pragma unroll
    for (int u = 0; u < 16; u++) Ws4[t + u * 256] = Wg4[t + u * 256];

    float4*       is4 = (float4*)in_s;
    const float4* ig4 = (const float4*)(input + (size_t)rowbase * EMB);
#pragma unroll
    for (int u = 0; u < 8; u++) is4[t + u * 256] = ig4[t + u * 256];
    __syncthreads();

    const int dg = t & 15;            // dims 4*dg .. 4*dg+3
    const int r0 = (t >> 4) * 2;      // rows r0, r0+1
    float4 acc0 = make_float4(0.f, 0.f, 0.f, 0.f);
    float4 acc1 = make_float4(0.f, 0.f, 0.f, 0.f);

#pragma unroll 4
    for (int k = 0; k < EMB; k++) {
        float4 wv = Ws4[k * 16 + dg];
        float  a0 = in_s[r0 * EMB + k];
        float  a1 = in_s[(r0 + 1) * EMB + k];
        acc0.x += a0 * wv.x; acc0.y += a0 * wv.y; acc0.z += a0 * wv.z; acc0.w += a0 * wv.w;
        acc1.x += a1 * wv.x; acc1.y += a1 * wv.y; acc1.z += a1 * wv.z; acc1.w += a1 * wv.w;
    }

    *(float4*)&g_h[(size_t)(rowbase + r0) * NHID + dg * 4]     = acc0;
    *(float4*)&g_h[(size_t)(rowbase + r0 + 1) * NHID + dg * 4] = acc1;

    const float as0 = __ldg(a + 4 * dg),      as1 = __ldg(a + 4 * dg + 1);
    const float as2 = __ldg(a + 4 * dg + 2),  as3 = __ldg(a + 4 * dg + 3);
    const float ad0 = __ldg(a + 64 + 4 * dg), ad1 = __ldg(a + 64 + 4 * dg + 1);
    const float ad2 = __ldg(a + 64 + 4 * dg + 2), ad3 = __ldg(a + 64 + 4 * dg + 3);

    float p0s = acc0.x * as0 + acc0.y * as1 + acc0.z * as2 + acc0.w * as3;
    float p0d = acc0.x * ad0 + acc0.y * ad1 + acc0.z * ad2 + acc0.w * ad3;
    float p1s = acc1.x * as0 + acc1.y * as1 + acc1.z * as2 + acc1.w * as3;
    float p1d = acc1.x * ad0 + acc1.y * ad1 + acc1.z * ad2 + acc1.w * ad3;
#pragma unroll
    for (int o = 8; o > 0; o >>= 1) {
        p0s += __shfl_down_sync(0xffffffffu, p0s, o, 16);
        p0d += __shfl_down_sync(0xffffffffu, p0d, o, 16);
        p1s += __shfl_down_sync(0xffffffffu, p1s, o, 16);
        p1d += __shfl_down_sync(0xffffffffu, p1d, o, 16);
    }
    if (dg == 0) {
        g_ss[rowbase + r0]     = p0s * LOG2E;
        g_sd[rowbase + r0]     = p0d * LOG2E;
        g_ss[rowbase + r0 + 1] = p1s * LOG2E;
        g_sd[rowbase + r0 + 1] = p1d * LOG2E;
    }
}

// ---------------------------------------------------------------------------
// Kernel C: fused masked-softmax attention, software-pipelined, LDS-lean GEMM.
// 147 CTAs x 256 threads, 56 rows/CTA, j-tile = 128.
//
// Accumulator layout: f32x2 = (even-j partial, odd-j partial) for ONE dim.
//   - w stored plain f32: one uniform LDS.128 = {w[j..j+3]} = 2 fma-ready
//     f32x2 operands, feeding 4 FFMA2 each. No duplication MOVs.
//   - h tile transpose-packed in smem: h2[jp][d] = {h[2jp][d], h[2jp+1][d]};
//     lane loads its 2 dims as one conflict-free LDS.128.
// Per 4-j inner block: 9 LDS / 28 FFMA2  (was 18 LDS / 28 FFMA2).
// ---------------------------------------------------------------------------
__global__ __launch_bounds__(256, 1) void kC(const int* __restrict__ adj,
                                             float* __restrict__ out) {
    extern __shared__ char smem[];
    float* h2  = (float*)smem;                       // 64 jp x 64 dim-pairs: 32 KB
    float* w_s = (float*)(smem + 32768);             // 56 x 128 f32: 28 KB
    float* l_s = (float*)(smem + 32768 + 28672);     // 56 floats

    const int t    = threadIdx.x;
    const int lane = t & 31;
    const int warp = t >> 5;
    const int rowbase = blockIdx.x * RPC;
    const int j0 = lane * 4;            // phase-1 j slice
    const int c   = t & 15;             // transpose: dim group 4c..4c+3
    const int jp0 = t >> 4;             // transpose: jpair base 0..15

    // phase-1 row set (clamped for the partial last CTA)
    int   rowg[7];
    float si[7];
#pragma unroll
    for (int it = 0; it < 7; it++) {
        int rg = rowbase + warp + it * 8;
        rowg[it] = (rg < NN) ? rg : (NN - 1);
        si[it]   = g_ss[rowg[it]];
    }

    unsigned long long accA[7], accB[7];   // per row: dim d0 / dim d0+1 (j-split pairs)
    float lrow[7];
#pragma unroll
    for (int r = 0; r < 7; r++) { accA[r] = 0ULL; accB[r] = 0ULL; lrow[r] = 0.f; }

    // ---- prologue: prefetch tile 0 ----
    int4   apf[7];
    float4 ra[4], rb[4];
    float  wv[28];
    float4 sdv = *(const float4*)(g_sd + j0);
    {
        const float* hb = g_h;
#pragma unroll
        for (int u = 0; u < 4; u++) {
            int jp = jp0 + u * 16;
            ra[u] = *(const float4*)&hb[(2 * jp) * NHID + 4 * c];
            rb[u] = *(const float4*)&hb[(2 * jp + 1) * NHID + 4 * c];
        }
#pragma unroll
        for (int it = 0; it < 7; it++)
            apf[it] = *(const int4*)(adj + (size_t)rowg[it] * NN + j0);
#pragma unroll
        for (int it = 0; it < 7; it++) {
            float x0 = si[it] + sdv.x, x1 = si[it] + sdv.y;
            float x2 = si[it] + sdv.z, x3 = si[it] + sdv.w;
            float w0 = ex2_approx(fmaxf(x0, 0.2f * x0));
            float w1 = ex2_approx(fmaxf(x1, 0.2f * x1));
            float w2 = ex2_approx(fmaxf(x2, 0.2f * x2));
            float w3 = ex2_approx(fmaxf(x3, 0.2f * x3));
            w0 = (apf[it].x > 0) ? w0 : 0.f;
            w1 = (apf[it].y > 0) ? w1 : 0.f;
            w2 = (apf[it].z > 0) ? w2 : 0.f;
            w3 = (apf[it].w > 0) ? w3 : 0.f;
            wv[it * 4 + 0] = w0; wv[it * 4 + 1] = w1;
            wv[it * 4 + 2] = w2; wv[it * 4 + 3] = w3;
            lrow[it] += (w0 + w1) + (w2 + w3);
        }
    }

    const float* wr = &w_s[(warp * 7) * JT];

    for (int jb = 0; jb < NN; jb += JT) {
        // ---- commit prefetched tile to smem ----
        // h: transpose-pack {h[2jp][d], h[2jp+1][d]} pairs, dims 4c..4c+3
#pragma unroll
        for (int u = 0; u < 4; u++) {
            int jp = jp0 + u * 16;
            float* d = &h2[jp * 128 + 8 * c];
            ((float4*)d)[0] = make_float4(ra[u].x, rb[u].x, ra[u].y, rb[u].y);
            ((float4*)d)[1] = make_float4(ra[u].z, rb[u].z, ra[u].w, rb[u].w);
        }
        // w: plain f32, contiguous conflict-free float4 stores
#pragma unroll
        for (int it = 0; it < 7; it++) {
            int i = warp + it * 8;
            *(float4*)&w_s[i * JT + j0] =
                make_float4(wv[it * 4 + 0], wv[it * 4 + 1], wv[it * 4 + 2], wv[it * 4 + 3]);
        }
        __syncthreads();

        const int  jn   = jb + JT;
        const bool more = jn < NN;
        if (more) {
            const float* hb = g_h + (size_t)jn * NHID;
#pragma unroll
            for (int u = 0; u < 4; u++) {
                int jp = jp0 + u * 16;
                ra[u] = *(const float4*)&hb[(2 * jp) * NHID + 4 * c];
                rb[u] = *(const float4*)&hb[(2 * jp + 1) * NHID + 4 * c];
            }
#pragma unroll
            for (int it = 0; it < 7; it++)
                apf[it] = *(const int4*)(adj + (size_t)rowg[it] * NN + jn + j0);
            sdv = *(const float4*)(g_sd + jn + j0);
        }

        // ---- GEMM first half (covers LDG latency) ----
#pragma unroll 4
        for (int j = 0; j < 64; j += 4) {
            const int jp = j >> 1;
            ulonglong2 hA = *(const ulonglong2*)&h2[jp * 128 + lane * 4];
            ulonglong2 hB = *(const ulonglong2*)&h2[(jp + 1) * 128 + lane * 4];
#pragma unroll
            for (int r = 0; r < 7; r++) {
                ulonglong2 wp = *(const ulonglong2*)&wr[r * JT + j];
                fma2(accA[r], wp.x, hA.x);
                fma2(accB[r], wp.x, hA.y);
                fma2(accA[r], wp.y, hB.x);
                fma2(accB[r], wp.y, hB.y);
            }
        }

        // ---- compute next tile's w (MUFU overlaps second GEMM half) ----
        if (more) {
#pragma unroll
            for (int it = 0; it < 7; it++) {
                float x0 = si[it] + sdv.x, x1 = si[it] + sdv.y;
                float x2 = si[it] + sdv.z, x3 = si[it] + sdv.w;
                float w0 = ex2_approx(fmaxf(x0, 0.2f * x0));
                float w1 = ex2_approx(fmaxf(x1, 0.2f * x1));
                float w2 = ex2_approx(fmaxf(x2, 0.2f * x2));
                float w3 = ex2_approx(fmaxf(x3, 0.2f * x3));
                w0 = (apf[it].x > 0) ? w0 : 0.f;
                w1 = (apf[it].y > 0) ? w1 : 0.f;
                w2 = (apf[it].z > 0) ? w2 : 0.f;
                w3 = (apf[it].w > 0) ? w3 : 0.f;
                wv[it * 4 + 0] = w0; wv[it * 4 + 1] = w1;
                wv[it * 4 + 2] = w2; wv[it * 4 + 3] = w3;
                lrow[it] += (w0 + w1) + (w2 + w3);
            }
        }

        // ---- GEMM second half ----
#pragma unroll 4
        for (int j = 64; j < 128; j += 4) {
            const int jp = j >> 1;
            ulonglong2 hA = *(const ulonglong2*)&h2[jp * 128 + lane * 4];
            ulonglong2 hB = *(const ulonglong2*)&h2[(jp + 1) * 128 + lane * 4];
#pragma unroll
            for (int r = 0; r < 7; r++) {
                ulonglong2 wp = *(const ulonglong2*)&wr[r * JT + j];
                fma2(accA[r], wp.x, hA.x);
                fma2(accB[r], wp.x, hA.y);
                fma2(accA[r], wp.y, hB.x);
                fma2(accB[r], wp.y, hB.y);
            }
        }
        __syncthreads();
    }

    // ---- epilogue: row-sum reduce once, normalize, store ----
#pragma unroll
    for (int it = 0; it < 7; it++) {
        float s = lrow[it];
#pragma unroll
        for (int o = 16; o > 0; o >>= 1)
            s += __shfl_xor_sync(0xffffffffu, s, o);
        if (lane == 0) l_s[warp + it * 8] = s;
    }
    __syncthreads();

#pragma unroll
    for (int r = 0; r < 7; r++) {
        const int i  = warp * 7 + r;
        const int rg = rowbase + i;
        if (rg < NN) {
            const float inv = 1.0f / l_s[i];
            unsigned long long va = accA[r], vb = accB[r];
            float sA = __uint_as_float((unsigned)(va & 0xffffffffULL)) +
                       __uint_as_float((unsigned)(va >> 32));
            float sB = __uint_as_float((unsigned)(vb & 0xffffffffULL)) +
                       __uint_as_float((unsigned)(vb >> 32));
            *(float2*)&out[(size_t)rg * NHID + lane * 2] =
                make_float2(sA * inv, sB * inv);
        }
    }
}

// ---------------------------------------------------------------------------
extern "C" void kernel_launch(void* const* d_in, const int* in_sizes, int n_in,
                              void* d_out, int out_size) {
    const float* input = (const float*)d_in[0];   // [8192, 256] f32
    const int*   adj   = (const int*)d_in[1];     // [8192, 8192] i32
    const float* W     = (const float*)d_in[2];   // [256, 64] f32
    const float* a     = (const float*)d_in[3];   // [128] f32
    float* out = (float*)d_out;                   // [8192, 64] f32

    const int smemA = (EMB * NHID + 32 * EMB) * sizeof(float);     // 96 KB
    const int smemC = 32768 + 28672 + 64 * (int)sizeof(float);     // ~60 KB
    cudaFuncSetAttribute(kA, cudaFuncAttributeMaxDynamicSharedMemorySize, smemA);
    cudaFuncSetAttribute(kC, cudaFuncAttributeMaxDynamicSharedMemorySize, smemC);

    kA<<<NN / 32, 256, smemA>>>(input, W, a);
    kC<<<(NN + RPC - 1) / RPC, 256, smemC>>>(adj, out);
}

// round 11
// speedup vs baseline: 1.6069x; 1.0487x over previous
#include <cuda_runtime.h>
#include <cstdint>

#define NN    8192
#define EMB   256
#define NHID  64
#define LOG2E 1.4426950408889634f
#define RPC   56          // rows per CTA in kC
#define JT    128         // j-tile

// Scratch (static device arrays; no allocation).
__device__ float g_h[NN * NHID];   // h = input @ W  (2 MB, L2-resident)
__device__ float g_ss[NN];         // s_src * log2e
__device__ float g_sd[NN];         // s_dst * log2e

__device__ __forceinline__ void fma2(unsigned long long& acc,
                                     unsigned long long w,
                                     unsigned long long h) {
    asm("fma.rn.f32x2 %0, %1, %2, %0;" : "+l"(acc) : "l"(w), "l"(h));
}
__device__ __forceinline__ float ex2_approx(float x) {
    float r;
    asm("ex2.approx.ftz.f32 %0, %1;" : "=f"(r) : "f"(x));
    return r;
}

// ---------------------------------------------------------------------------
// Kernel A: h = input @ W, fused with s_src/s_dst computation.
// 256 blocks x 256 threads, 32 rows/block.  (17us; not the bottleneck)
// ---------------------------------------------------------------------------
__global__ __launch_bounds__(256) void kA(const float* __restrict__ input,
                                          const float* __restrict__ W,
                                          const float* __restrict__ a) {
    extern __shared__ float smemA[];
    float* W_s  = smemA;                 // 256*64 floats (64 KB)
    float* in_s = smemA + EMB * NHID;    // 32*256 floats (32 KB)

    const int t = threadIdx.x;
    const int rowbase = blockIdx.x * 32;

    float4*       Ws4 = (float4*)W_s;
    const float4* Wg4 = (const float4*)W;
#pragma unroll
    for (int u = 0; u < 16; u++) Ws4[t + u * 256] = Wg4[t + u * 256];

    float4*       is4 = (float4*)in_s;
    const float4* ig4 = (const float4*)(input + (size_t)rowbase * EMB);
#pragma unroll
    for (int u = 0; u < 8; u++) is4[t + u * 256] = ig4[t + u * 256];
    __syncthreads();

    const int dg = t & 15;            // dims 4*dg .. 4*dg+3
    const int r0 = (t >> 4) * 2;      // rows r0, r0+1
    float4 acc0 = make_float4(0.f, 0.f, 0.f, 0.f);
    float4 acc1 = make_float4(0.f, 0.f, 0.f, 0.f);

#pragma unroll 4
    for (int k = 0; k < EMB; k++) {
        float4 wv = Ws4[k * 16 + dg];
        float  a0 = in_s[r0 * EMB + k];
        float  a1 = in_s[(r0 + 1) * EMB + k];
        acc0.x += a0 * wv.x; acc0.y += a0 * wv.y; acc0.z += a0 * wv.z; acc0.w += a0 * wv.w;
        acc1.x += a1 * wv.x; acc1.y += a1 * wv.y; acc1.z += a1 * wv.z; acc1.w += a1 * wv.w;
    }

    *(float4*)&g_h[(size_t)(rowbase + r0) * NHID + dg * 4]     = acc0;
    *(float4*)&g_h[(size_t)(rowbase + r0 + 1) * NHID + dg * 4] = acc1;

    const float as0 = __ldg(a + 4 * dg),      as1 = __ldg(a + 4 * dg + 1);
    const float as2 = __ldg(a + 4 * dg + 2),  as3 = __ldg(a + 4 * dg + 3);
    const float ad0 = __ldg(a + 64 + 4 * dg), ad1 = __ldg(a + 64 + 4 * dg + 1);
    const float ad2 = __ldg(a + 64 + 4 * dg + 2), ad3 = __ldg(a + 64 + 4 * dg + 3);

    float p0s = acc0.x * as0 + acc0.y * as1 + acc0.z * as2 + acc0.w * as3;
    float p0d = acc0.x * ad0 + acc0.y * ad1 + acc0.z * ad2 + acc0.w * ad3;
    float p1s = acc1.x * as0 + acc1.y * as1 + acc1.z * as2 + acc1.w * as3;
    float p1d = acc1.x * ad0 + acc1.y * ad1 + acc1.z * ad2 + acc1.w * ad3;
#pragma unroll
    for (int o = 8; o > 0; o >>= 1) {
        p0s += __shfl_down_sync(0xffffffffu, p0s, o, 16);
        p0d += __shfl_down_sync(0xffffffffu, p0d, o, 16);
        p1s += __shfl_down_sync(0xffffffffu, p1s, o, 16);
        p1d += __shfl_down_sync(0xffffffffu, p1d, o, 16);
    }
    if (dg == 0) {
        g_ss[rowbase + r0]     = p0s * LOG2E;
        g_sd[rowbase + r0]     = p0d * LOG2E;
        g_ss[rowbase + r0 + 1] = p1s * LOG2E;
        g_sd[rowbase + r0 + 1] = p1d * LOG2E;
    }
}

// ---------------------------------------------------------------------------
// Kernel C: fused masked-softmax attention, software-pipelined, LDS-lean GEMM.
// 147 CTAs x 256 threads, 56 rows/CTA, j-tile = 128.
//
// Accumulator layout: f32x2 = (even-j partial, odd-j partial) for ONE dim.
//   - w stored plain f32: one uniform LDS.128 = {w[j..j+3]} = 2 fma-ready
//     f32x2 operands, feeding 4 FFMA2 each. No duplication MOVs.
//   - h tile transpose-packed in smem: h2[jp][d] = {h[2jp][d], h[2jp+1][d]};
//     lane loads its 2 dims as one conflict-free LDS.128.
// Per 4-j inner block: 9 LDS / 28 FFMA2  (was 18 LDS / 28 FFMA2).
// ---------------------------------------------------------------------------
__global__ __launch_bounds__(256, 1) void kC(const int* __restrict__ adj,
                                             float* __restrict__ out) {
    extern __shared__ char smem[];
    float* h2  = (float*)smem;                       // 64 jp x 64 dim-pairs: 32 KB
    float* w_s = (float*)(smem + 32768);             // 56 x 128 f32: 28 KB
    float* l_s = (float*)(smem + 32768 + 28672);     // 56 floats

    const int t    = threadIdx.x;
    const int lane = t & 31;
    const int warp = t >> 5;
    const int rowbase = blockIdx.x * RPC;
    const int j0 = lane * 4;            // phase-1 j slice
    const int c   = t & 15;             // transpose: dim group 4c..4c+3
    const int jp0 = t >> 4;             // transpose: jpair base 0..15

    // phase-1 row set (clamped for the partial last CTA)
    int   rowg[7];
    float si[7];
#pragma unroll
    for (int it = 0; it < 7; it++) {
        int rg = rowbase + warp + it * 8;
        rowg[it] = (rg < NN) ? rg : (NN - 1);
        si[it]   = g_ss[rowg[it]];
    }

    unsigned long long accA[7], accB[7];   // per row: dim d0 / dim d0+1 (j-split pairs)
    float lrow[7];
#pragma unroll
    for (int r = 0; r < 7; r++) { accA[r] = 0ULL; accB[r] = 0ULL; lrow[r] = 0.f; }

    // ---- prologue: prefetch tile 0 ----
    int4   apf[7];
    float4 ra[4], rb[4];
    float  wv[28];
    float4 sdv = *(const float4*)(g_sd + j0);
    {
        const float* hb = g_h;
#pragma unroll
        for (int u = 0; u < 4; u++) {
            int jp = jp0 + u * 16;
            ra[u] = *(const float4*)&hb[(2 * jp) * NHID + 4 * c];
            rb[u] = *(const float4*)&hb[(2 * jp + 1) * NHID + 4 * c];
        }
#pragma unroll
        for (int it = 0; it < 7; it++)
            apf[it] = *(const int4*)(adj + (size_t)rowg[it] * NN + j0);
#pragma unroll
        for (int it = 0; it < 7; it++) {
            float x0 = si[it] + sdv.x, x1 = si[it] + sdv.y;
            float x2 = si[it] + sdv.z, x3 = si[it] + sdv.w;
            float w0 = ex2_approx(fmaxf(x0, 0.2f * x0));
            float w1 = ex2_approx(fmaxf(x1, 0.2f * x1));
            float w2 = ex2_approx(fmaxf(x2, 0.2f * x2));
            float w3 = ex2_approx(fmaxf(x3, 0.2f * x3));
            w0 = (apf[it].x > 0) ? w0 : 0.f;
            w1 = (apf[it].y > 0) ? w1 : 0.f;
            w2 = (apf[it].z > 0) ? w2 : 0.f;
            w3 = (apf[it].w > 0) ? w3 : 0.f;
            wv[it * 4 + 0] = w0; wv[it * 4 + 1] = w1;
            wv[it * 4 + 2] = w2; wv[it * 4 + 3] = w3;
            lrow[it] += (w0 + w1) + (w2 + w3);
        }
    }

    const float* wr = &w_s[(warp * 7) * JT];

    for (int jb = 0; jb < NN; jb += JT) {
        // ---- commit prefetched tile to smem ----
        // h: transpose-pack {h[2jp][d], h[2jp+1][d]} pairs, dims 4c..4c+3
#pragma unroll
        for (int u = 0; u < 4; u++) {
            int jp = jp0 + u * 16;
            float* d = &h2[jp * 128 + 8 * c];
            ((float4*)d)[0] = make_float4(ra[u].x, rb[u].x, ra[u].y, rb[u].y);
            ((float4*)d)[1] = make_float4(ra[u].z, rb[u].z, ra[u].w, rb[u].w);
        }
        // w: plain f32, contiguous conflict-free float4 stores
#pragma unroll
        for (int it = 0; it < 7; it++) {
            int i = warp + it * 8;
            *(float4*)&w_s[i * JT + j0] =
                make_float4(wv[it * 4 + 0], wv[it * 4 + 1], wv[it * 4 + 2], wv[it * 4 + 3]);
        }
        __syncthreads();

        const int  jn   = jb + JT;
        const bool more = jn < NN;
        if (more) {
            const float* hb = g_h + (size_t)jn * NHID;
#pragma unroll
            for (int u = 0; u < 4; u++) {
                int jp = jp0 + u * 16;
                ra[u] = *(const float4*)&hb[(2 * jp) * NHID + 4 * c];
                rb[u] = *(const float4*)&hb[(2 * jp + 1) * NHID + 4 * c];
            }
#pragma unroll
            for (int it = 0; it < 7; it++)
                apf[it] = *(const int4*)(adj + (size_t)rowg[it] * NN + jn + j0);
            sdv = *(const float4*)(g_sd + jn + j0);
        }

        // ---- GEMM first half (covers LDG latency) ----
#pragma unroll 4
        for (int j = 0; j < 64; j += 4) {
            const int jp = j >> 1;
            ulonglong2 hA = *(const ulonglong2*)&h2[jp * 128 + lane * 4];
            ulonglong2 hB = *(const ulonglong2*)&h2[(jp + 1) * 128 + lane * 4];
#pragma unroll
            for (int r = 0; r < 7; r++) {
                ulonglong2 wp = *(const ulonglong2*)&wr[r * JT + j];
                fma2(accA[r], wp.x, hA.x);
                fma2(accB[r], wp.x, hA.y);
                fma2(accA[r], wp.y, hB.x);
                fma2(accB[r], wp.y, hB.y);
            }
        }

        // ---- compute next tile's w (MUFU overlaps second GEMM half) ----
        if (more) {
#pragma unroll
            for (int it = 0; it < 7; it++) {
                float x0 = si[it] + sdv.x, x1 = si[it] + sdv.y;
                float x2 = si[it] + sdv.z, x3 = si[it] + sdv.w;
                float w0 = ex2_approx(fmaxf(x0, 0.2f * x0));
                float w1 = ex2_approx(fmaxf(x1, 0.2f * x1));
                float w2 = ex2_approx(fmaxf(x2, 0.2f * x2));
                float w3 = ex2_approx(fmaxf(x3, 0.2f * x3));
                w0 = (apf[it].x > 0) ? w0 : 0.f;
                w1 = (apf[it].y > 0) ? w1 : 0.f;
                w2 = (apf[it].z > 0) ? w2 : 0.f;
                w3 = (apf[it].w > 0) ? w3 : 0.f;
                wv[it * 4 + 0] = w0; wv[it * 4 + 1] = w1;
                wv[it * 4 + 2] = w2; wv[it * 4 + 3] = w3;
                lrow[it] += (w0 + w1) + (w2 + w3);
            }
        }

        // ---- GEMM second half ----
#pragma unroll 4
        for (int j = 64; j < 128; j += 4) {
            const int jp = j >> 1;
            ulonglong2 hA = *(const ulonglong2*)&h2[jp * 128 + lane * 4];
            ulonglong2 hB = *(const ulonglong2*)&h2[(jp + 1) * 128 + lane * 4];
#pragma unroll
            for (int r = 0; r < 7; r++) {
                ulonglong2 wp = *(const ulonglong2*)&wr[r * JT + j];
                fma2(accA[r], wp.x, hA.x);
                fma2(accB[r], wp.x, hA.y);
                fma2(accA[r], wp.y, hB.x);
                fma2(accB[r], wp.y, hB.y);
            }
        }
        __syncthreads();
    }

    // ---- epilogue: row-sum reduce once, normalize, store ----
#pragma unroll
    for (int it = 0; it < 7; it++) {
        float s = lrow[it];
#pragma unroll
        for (int o = 16; o > 0; o >>= 1)
            s += __shfl_xor_sync(0xffffffffu, s, o);
        if (lane == 0) l_s[warp + it * 8] = s;
    }
    __syncthreads();

#pragma unroll
    for (int r = 0; r < 7; r++) {
        const int i  = warp * 7 + r;
        const int rg = rowbase + i;
        if (rg < NN) {
            const float inv = 1.0f / l_s[i];
            unsigned long long va = accA[r], vb = accB[r];
            float sA = __uint_as_float((unsigned)(va & 0xffffffffULL)) +
                       __uint_as_float((unsigned)(va >> 32));
            float sB = __uint_as_float((unsigned)(vb & 0xffffffffULL)) +
                       __uint_as_float((unsigned)(vb >> 32));
            *(float2*)&out[(size_t)rg * NHID + lane * 2] =
                make_float2(sA * inv, sB * inv);
        }
    }
}

// ---------------------------------------------------------------------------
extern "C" void kernel_launch(void* const* d_in, const int* in_sizes, int n_in,
                              void* d_out, int out_size) {
    const float* input = (const float*)d_in[0];   // [8192, 256] f32
    const int*   adj   = (const int*)d_in[1];     // [8192, 8192] i32
    const float* W     = (const float*)d_in[2];   // [256, 64] f32
    const float* a     = (const float*)d_in[3];   // [128] f32
    float* out = (float*)d_out;                   // [8192, 64] f32

    const int smemA = (EMB * NHID + 32 * EMB) * sizeof(float);     // 96 KB
    const int smemC = 32768 + 28672 + 64 * (int)sizeof(float);     // ~60 KB
    cudaFuncSetAttribute(kA, cudaFuncAttributeMaxDynamicSharedMemorySize, smemA);
    cudaFuncSetAttribute(kC, cudaFuncAttributeMaxDynamicSharedMemorySize, smemC);

    kA<<<NN / 32, 256, smemA>>>(input, W, a);
    kC<<<(NN + RPC - 1) / RPC, 256, smemC>>>(adj, out);
}